// round 9
// baseline (speedup 1.0000x reference)
#include <cuda_runtime.h>
#include <cuda_bf16.h>
#include <math.h>

// Problem constants
#define BB   4
#define SS   2048
#define DD   1024
#define HH   16
#define DH   64
#define KTOP 409        // max(S // 5, 1)

// ---------------- scratch (device globals; no allocation allowed) ----------------
__device__ float   g_Qt[(size_t)BB * DD * SS];   // Q transposed: [b*D + j][s]
__device__ float   g_Kt[(size_t)BB * DD * SS];   // K transposed
__device__ float2  g_P[(size_t)BB * DD * SS];    // per-(b,h,d) spectrum product Q*conj(K)
__device__ float   g_att[BB * DD];               // attended, flattened heads
__device__ float   g_y[BB * DD];                 // final per-batch output row
__device__ float2  g_twf[1024];                  // FFT twiddles exp(-2*pi*i*j/2048)

// ---------------- helpers ----------------
// In-place radix-2 DIT FFT of 2048 complex floats in shared memory.
// Input must be pre-bit-reversed. 256 threads. Caller syncs before the call.
__device__ void fft2048f(float2* z, const float2* tw) {
    int tid = threadIdx.x;
    for (int half = 1; half < 2048; half <<= 1) {
        int step = 1024 / half;  // twiddle stride
        for (int jj = tid; jj < 1024; jj += 256) {
            int p  = jj & (half - 1);
            int i0 = ((jj ^ p) << 1) | p;  // (jj - p)*2 + p
            int i1 = i0 + half;
            float2 w = tw[p * step];
            float2 v = z[i1];
            float tr = w.x * v.x - w.y * v.y;
            float ti = w.x * v.y + w.y * v.x;
            float2 u = z[i0];
            z[i0] = make_float2(u.x + tr, u.y + ti);
            z[i1] = make_float2(u.x - tr, u.y - ti);
        }
        __syncthreads();
    }
}

// Order-preserving float <-> uint encode (ascending uint order == ascending float order)
__device__ __forceinline__ unsigned int fenc(float v) {
    unsigned int u = __float_as_uint(v);
    return (u & 0x80000000u) ? ~u : (u | 0x80000000u);
}
__device__ __forceinline__ float fdec(unsigned int e) {
    unsigned int u = (e & 0x80000000u) ? (e & 0x7FFFFFFFu) : ~e;
    return __uint_as_float(u);
}

// ---------------- kernel 0: twiddle table ----------------
__global__ void tw_init_kernel() {
    int i = blockIdx.x * blockDim.x + threadIdx.x;
    if (i < 1024) {
        double ang = -2.0 * 3.14159265358979323846 * (double)i / 2048.0;
        g_twf[i] = make_float2((float)cos(ang), (float)sin(ang));
    }
}

// ---------------- kernel 1: SGEMM, transposed output, f32x2 packed FMA ----------------
// Ct[(b*D + j)*S + s] = sum_c X[(b*S+s)*D + c] * W[c*D + j] + bias[j]
#define BM 128
#define BN 128
#define BK 16
__global__ __launch_bounds__(256, 2)
void sgemm_tn_kernel(const float* __restrict__ X, const float* __restrict__ W,
                     const float* __restrict__ bias, int which) {
    float* Ct = which ? g_Kt : g_Qt;
    int b  = blockIdx.z;
    int j0 = blockIdx.x * BM;
    int s0 = blockIdx.y * BN;
    const float* Xb = X + (size_t)b * SS * DD;

    __shared__ __align__(16) float As[2][BK][BM];  // As[.][k][m] = W[(kt+k)*D + j0+m]
    __shared__ __align__(16) float Bs[2][BK][BN];  // Bs[.][k][n] = Xb[(s0+n)*D + kt+k]

    int tid = threadIdx.x;
    int tx = tid & 15, ty = tid >> 4;
    int m0 = tx * 8, n0 = ty * 8;

    // loader indices: two float4 loads each for A and B per thread
    int kA = tid >> 4;                 // same for both A loads
    int mA0 = (tid * 2) & 31;
    int mA1 = mA0 + 1;
    int nB = tid >> 1;                 // same for both B loads
    int kB0 = (tid * 2) & 3;
    int kB1 = kB0 + 1;

    unsigned long long acc2[8][4];     // packed f32x2 accumulators (m, n-pairs)
#pragma unroll
    for (int i = 0; i < 8; i++)
#pragma unroll
        for (int j = 0; j < 4; j++) acc2[i][j] = 0ull;

#define LOADG(kt, pa0, pa1, pb0, pb1) do {                                         \
        pa0 = *(const float4*)&W[(size_t)((kt) + kA) * DD + j0 + mA0 * 4];         \
        pa1 = *(const float4*)&W[(size_t)((kt) + kA) * DD + j0 + mA1 * 4];         \
        pb0 = *(const float4*)&Xb[(size_t)(s0 + nB) * DD + (kt) + kB0 * 4];        \
        pb1 = *(const float4*)&Xb[(size_t)(s0 + nB) * DD + (kt) + kB1 * 4];        \
    } while (0)

#define STORES(buf, pa0, pa1, pb0, pb1) do {                                       \
        *(float4*)&As[buf][kA][mA0 * 4] = pa0;                                     \
        *(float4*)&As[buf][kA][mA1 * 4] = pa1;                                     \
        Bs[buf][kB0 * 4 + 0][nB] = pb0.x;  Bs[buf][kB0 * 4 + 1][nB] = pb0.y;       \
        Bs[buf][kB0 * 4 + 2][nB] = pb0.z;  Bs[buf][kB0 * 4 + 3][nB] = pb0.w;       \
        Bs[buf][kB1 * 4 + 0][nB] = pb1.x;  Bs[buf][kB1 * 4 + 1][nB] = pb1.y;       \
        Bs[buf][kB1 * 4 + 2][nB] = pb1.z;  Bs[buf][kB1 * 4 + 3][nB] = pb1.w;       \
    } while (0)

    {
        float4 pa0, pa1, pb0, pb1;
        LOADG(0, pa0, pa1, pb0, pb1);
        STORES(0, pa0, pa1, pb0, pb1);
    }
    __syncthreads();

    int cur = 0;
    for (int kt = 0; kt < DD; kt += BK) {
        bool has = (kt + BK) < DD;
        float4 qa0, qa1, qb0, qb1;
        if (has) LOADG(kt + BK, qa0, qa1, qb0, qb1);

        // compute on buffer `cur`
#pragma unroll
        for (int k = 0; k < BK; k++) {
            unsigned long long a2[8], b2[4];
#pragma unroll
            for (int i = 0; i < 8; i++) {
                float a = As[cur][k][m0 + i];
                asm("mov.b64 %0, {%1, %1};" : "=l"(a2[i]) : "f"(a));
            }
#pragma unroll
            for (int j = 0; j < 4; j++)
                b2[j] = *(const unsigned long long*)&Bs[cur][k][n0 + 2 * j];
#pragma unroll
            for (int i = 0; i < 8; i++)
#pragma unroll
                for (int j = 0; j < 4; j++)
                    asm("fma.rn.f32x2 %0, %1, %2, %0;"
                        : "+l"(acc2[i][j]) : "l"(a2[i]), "l"(b2[j]));
        }

        if (has) STORES(cur ^ 1, qa0, qa1, qb0, qb1);
        __syncthreads();
        cur ^= 1;
    }

#pragma unroll
    for (int i = 0; i < 8; i++) {
        float bj = bias[j0 + m0 + i];
        float r[8];
#pragma unroll
        for (int j = 0; j < 4; j++) {
            float lo, hi;
            asm("mov.b64 {%0, %1}, %2;" : "=f"(lo), "=f"(hi) : "l"(acc2[i][j]));
            r[2 * j]     = lo + bj;
            r[2 * j + 1] = hi + bj;
        }
        float* row = Ct + (size_t)(b * DD + j0 + m0 + i) * SS + s0 + n0;
        *(float4*)row       = make_float4(r[0], r[1], r[2], r[3]);
        *(float4*)(row + 4) = make_float4(r[4], r[5], r[6], r[7]);
    }
#undef LOADG
#undef STORES
}

// ---------------- kernel 2: packed forward FFT of (q + i*k), per (b,h,d) ----------------
// Writes per-channel spectrum product Q[f]*conj(K[f]) into g_P (no atomics).
__global__ void fft_qk_kernel() {
    int bhd = blockIdx.x;                 // 0..4095, == b*D + h*64 + d
    const float* qr = g_Qt + (size_t)bhd * SS;
    const float* kr = g_Kt + (size_t)bhd * SS;

    __shared__ float2 z[2048];            // 16KB
    __shared__ float2 tw[1024];           // 8KB

    int tid = threadIdx.x;
    for (int i = tid; i < 1024; i += 256) tw[i] = g_twf[i];
    for (int s = tid; s < 2048; s += 256) {
        int rs = __brev((unsigned)s) >> 21;         // 11-bit reversal
        z[rs] = make_float2(qr[s], kr[s]);
    }
    __syncthreads();

    fft2048f(z, tw);

    // Unpack: Z = FFT(q + i k). Q[f] = (Z[f]+conj(Z[N-f]))/2, K[f] = (Z[f]-conj(Z[N-f]))/(2i)
    for (int f = tid; f < 2048; f += 256) {
        float2 Zf = z[f];
        float2 Zc = z[(2048 - f) & 2047];
        float Qr =  0.5f * (Zf.x + Zc.x);
        float Qi =  0.5f * (Zf.y - Zc.y);
        float Kr =  0.5f * (Zf.y + Zc.y);
        float Ki = -0.5f * (Zf.x - Zc.x);
        // P = Q * conj(K)
        g_P[(size_t)bhd * SS + f] = make_float2(Qr * Kr + Qi * Ki, Qi * Kr - Qr * Ki);
    }
}

// ---------------- kernel 3: reduce over d, inverse FFT, top-k, softmax, gather ----------------
__global__ void corr_topk_kernel(const float* __restrict__ xv,
                                 const float* __restrict__ wv,
                                 const float* __restrict__ bv) {
    int bh = blockIdx.x;       // 0..63
    int b = bh >> 4, h = bh & 15;

    __shared__ float2 z[2048];                      // 16KB
    __shared__ float2 tw[1024];                     // 8KB
    __shared__ unsigned long long key[2048];        // 16KB
    __shared__ float zv[1024];                      // 4KB
    __shared__ float red[256];                      // 1KB

    int tid = threadIdx.x;
    for (int i = tid; i < 1024; i += 256) tw[i] = g_twf[i];

    // Sum spectra over channels d; load conj(P) bit-reversed (iFFT via conj trick).
    const float2* Pbase = g_P + (size_t)bh * DH * SS;
    for (int f = tid; f < 2048; f += 256) {
        float sr = 0.0f, si = 0.0f;
        for (int d = 0; d < DH; d++) {
            float2 p = Pbase[(size_t)d * SS + f];
            sr += p.x;
            si += p.y;
        }
        int rf = __brev((unsigned)f) >> 21;
        z[rf] = make_float2(sr, -si);
    }
    __syncthreads();

    fft2048f(z, tw);

    // mean_corr[t] = Re(FFT(conj(P)))[t] / N / (dh*sqrt(dh));  N=2048, dh*sqrt(dh)=512
    // Encode as sortable 64-bit key: value desc primary, index asc on ties.
    for (int t = tid; t < 2048; t += 256) {
        float v = z[t].x * (1.0f / (2048.0f * 512.0f));
        key[t] = ((unsigned long long)fenc(v) << 32) | (unsigned)(2047 - t);
    }
    __syncthreads();

    // Bitonic sort, descending on the combined key (== lax.top_k order)
    for (int k = 2; k <= 2048; k <<= 1) {
        for (int j = k >> 1; j > 0; j >>= 1) {
            for (int t = tid; t < 2048; t += 256) {
                int ixj = t ^ j;
                if (ixj > t) {
                    unsigned long long A = key[t], Bv = key[ixj];
                    bool desc = ((t & k) == 0);
                    bool sw = desc ? (Bv > A) : (A > Bv);
                    if (sw) { key[t] = Bv; key[ixj] = A; }
                }
            }
            __syncthreads();
        }
    }

    // Softmax over top KTOP values
    float maxv = fdec((unsigned)(key[0] >> 32));
    float lsum = 0.0f;
    for (int k = tid; k < KTOP; k += 256) lsum += expf(fdec((unsigned)(key[k] >> 32)) - maxv);
    red[tid] = lsum;
    for (int off = 128; off > 0; off >>= 1) {
        __syncthreads();
        if (tid < off) red[tid] += red[tid + off];
    }
    __syncthreads();
    float total = red[0];
    __syncthreads();

    // z[k] = (weight_k, index_k) for k < KTOP (z free after key build)
    for (int k = tid; k < KTOP; k += 256) {
        unsigned long long K = key[k];
        float v = fdec((unsigned)(K >> 32));
        int idx = 2047 - (int)(K & 0xFFFFFFFFull);
        z[k] = make_float2(expf(v - maxv) / total, (float)idx);
    }
    __syncthreads();

    // zv[c] = sum_k w_k * xv[b, idx_k, c]
    for (int c = tid; c < DD; c += 256) {
        float acc = 0.0f;
        for (int k = 0; k < KTOP; k++) {
            float2 wk = z[k];
            acc += wk.x * xv[((size_t)(b * SS + (int)wk.y)) * DD + c];
        }
        zv[c] = acc;
    }
    __syncthreads();

    // attended[j = h*64+dd] = sum_c zv[c] * wv[c, j] + bv[j]   (sum of weights == 1)
    if (tid < DH) {
        int j = h * DH + tid;
        float acc = 0.0f;
        for (int c = 0; c < DD; c++) acc += zv[c] * wv[(size_t)c * DD + j];
        g_att[b * DD + j] = acc + bv[j];
    }
}

// ---------------- kernel 4: y[b] = attended[b] @ wo + bo ----------------
__global__ void proj_y_kernel(const float* __restrict__ wo, const float* __restrict__ bo) {
    int b = blockIdx.x;
    int j = threadIdx.x;  // 1024 threads
    __shared__ float av[DD];
    av[j] = g_att[b * DD + j];
    __syncthreads();
    float acc = 0.0f;
    for (int i = 0; i < DD; i++) acc += av[i] * wo[(size_t)i * DD + j];
    g_y[b * DD + j] = acc + bo[j];
}

// ---------------- kernel 5: broadcast across sequence ----------------
__global__ void bcast_kernel(float* __restrict__ out) {
    int idx = blockIdx.x * blockDim.x + threadIdx.x;  // over B*S*D/4 float4s
    int j4 = idx & 255;          // D/4 = 256
    int bs = idx >> 8;           // 0..8191
    int b  = bs >> 11;           // /2048
    ((float4*)out)[idx] = ((const float4*)g_y)[b * 256 + j4];
}

// ---------------- launch ----------------
extern "C" void kernel_launch(void* const* d_in, const int* in_sizes, int n_in,
                              void* d_out, int out_size) {
    const float* xq = (const float*)d_in[0];
    const float* xk = (const float*)d_in[1];
    const float* xv = (const float*)d_in[2];
    const float* wq = (const float*)d_in[3];
    const float* bq = (const float*)d_in[4];
    const float* wk = (const float*)d_in[5];
    const float* bk = (const float*)d_in[6];
    const float* wv = (const float*)d_in[7];
    const float* bv = (const float*)d_in[8];
    const float* wo = (const float*)d_in[9];
    const float* bo = (const float*)d_in[10];
    float* out = (float*)d_out;

    tw_init_kernel<<<4, 256>>>();
    sgemm_tn_kernel<<<dim3(DD / BM, SS / BN, BB), 256>>>(xq, wq, bq, 0);
    sgemm_tn_kernel<<<dim3(DD / BM, SS / BN, BB), 256>>>(xk, wk, bk, 1);
    fft_qk_kernel<<<BB * DD, 256>>>();
    corr_topk_kernel<<<BB * HH, 256>>>(xv, wv, bv);
    proj_y_kernel<<<BB, DD>>>(wo, bo);
    bcast_kernel<<<(BB * SS * DD / 4) / 256, 256>>>(out);
}

// round 10
// speedup vs baseline: 1.0112x; 1.0112x over previous
#include <cuda_runtime.h>
#include <cuda_bf16.h>
#include <math.h>

// Problem constants
#define BB   4
#define SS   2048
#define DD   1024
#define HH   16
#define DH   64
#define KTOP 409        // max(S // 5, 1)

// ---------------- scratch (device globals; no allocation allowed) ----------------
__device__ float   g_Qt[(size_t)BB * DD * SS];   // Q transposed: [b*D + j][s]
__device__ float   g_Kt[(size_t)BB * DD * SS];   // K transposed
__device__ float2  g_P[(size_t)BB * DD * SS];    // per-(b,h,d) spectrum product Q*conj(K)
__device__ float   g_att[BB * DD];               // attended, flattened heads
__device__ float   g_y[BB * DD];                 // final per-batch output row
__device__ float2  g_twf[1024];                  // FFT twiddles exp(-2*pi*i*j/2048)

// ---------------- helpers ----------------
// In-place radix-2 DIT FFT of 2048 complex floats in shared memory.
// Input must be pre-bit-reversed. 256 threads. Caller syncs before the call.
__device__ void fft2048f(float2* z, const float2* tw) {
    int tid = threadIdx.x;
    for (int half = 1; half < 2048; half <<= 1) {
        int step = 1024 / half;  // twiddle stride
        for (int jj = tid; jj < 1024; jj += 256) {
            int p  = jj & (half - 1);
            int i0 = ((jj ^ p) << 1) | p;  // (jj - p)*2 + p
            int i1 = i0 + half;
            float2 w = tw[p * step];
            float2 v = z[i1];
            float tr = w.x * v.x - w.y * v.y;
            float ti = w.x * v.y + w.y * v.x;
            float2 u = z[i0];
            z[i0] = make_float2(u.x + tr, u.y + ti);
            z[i1] = make_float2(u.x - tr, u.y - ti);
        }
        __syncthreads();
    }
}

// Order-preserving float <-> uint encode (ascending uint order == ascending float order)
__device__ __forceinline__ unsigned int fenc(float v) {
    unsigned int u = __float_as_uint(v);
    return (u & 0x80000000u) ? ~u : (u | 0x80000000u);
}
__device__ __forceinline__ float fdec(unsigned int e) {
    unsigned int u = (e & 0x80000000u) ? (e & 0x7FFFFFFFu) : ~e;
    return __uint_as_float(u);
}

// ---------------- kernel 0: twiddle table ----------------
__global__ void tw_init_kernel() {
    int i = blockIdx.x * blockDim.x + threadIdx.x;
    if (i < 1024) {
        double ang = -2.0 * 3.14159265358979323846 * (double)i / 2048.0;
        g_twf[i] = make_float2((float)cos(ang), (float)sin(ang));
    }
}

// ---------------- kernel 1: SGEMM, transposed output, f32x2 packed FMA ----------------
// Ct[(b*D + j)*S + s] = sum_c X[(b*S+s)*D + c] * W[c*D + j] + bias[j]
#define BM 128
#define BN 128
#define BK 16
__global__ __launch_bounds__(256, 2)
void sgemm_tn_kernel(const float* __restrict__ X, const float* __restrict__ W,
                     const float* __restrict__ bias, int which) {
    float* Ct = which ? g_Kt : g_Qt;
    int b  = blockIdx.z;
    int j0 = blockIdx.x * BM;
    int s0 = blockIdx.y * BN;
    const float* Xb = X + (size_t)b * SS * DD;

    __shared__ __align__(16) float As[2][BK][BM];  // As[.][k][m] = W[(kt+k)*D + j0+m]
    __shared__ __align__(16) float Bs[2][BK][BN];  // Bs[.][k][n] = Xb[(s0+n)*D + kt+k]

    int tid = threadIdx.x;
    int tx = tid & 15, ty = tid >> 4;
    int m0 = tx * 8, n0 = ty * 8;

    // loader indices: two float4 loads each for A and B per thread
    int kA = tid >> 4;                 // same for both A loads
    int mA0 = (tid * 2) & 31;
    int mA1 = mA0 + 1;
    int nB = tid >> 1;                 // same for both B loads
    int kB0 = (tid * 2) & 3;
    int kB1 = kB0 + 1;

    unsigned long long acc2[8][4];     // packed f32x2 accumulators (m, n-pairs)
#pragma unroll
    for (int i = 0; i < 8; i++)
#pragma unroll
        for (int j = 0; j < 4; j++) acc2[i][j] = 0ull;

#define LOADG(kt, pa0, pa1, pb0, pb1) do {                                         \
        pa0 = *(const float4*)&W[(size_t)((kt) + kA) * DD + j0 + mA0 * 4];         \
        pa1 = *(const float4*)&W[(size_t)((kt) + kA) * DD + j0 + mA1 * 4];         \
        pb0 = *(const float4*)&Xb[(size_t)(s0 + nB) * DD + (kt) + kB0 * 4];        \
        pb1 = *(const float4*)&Xb[(size_t)(s0 + nB) * DD + (kt) + kB1 * 4];        \
    } while (0)

#define STORES(buf, pa0, pa1, pb0, pb1) do {                                       \
        *(float4*)&As[buf][kA][mA0 * 4] = pa0;                                     \
        *(float4*)&As[buf][kA][mA1 * 4] = pa1;                                     \
        Bs[buf][kB0 * 4 + 0][nB] = pb0.x;  Bs[buf][kB0 * 4 + 1][nB] = pb0.y;       \
        Bs[buf][kB0 * 4 + 2][nB] = pb0.z;  Bs[buf][kB0 * 4 + 3][nB] = pb0.w;       \
        Bs[buf][kB1 * 4 + 0][nB] = pb1.x;  Bs[buf][kB1 * 4 + 1][nB] = pb1.y;       \
        Bs[buf][kB1 * 4 + 2][nB] = pb1.z;  Bs[buf][kB1 * 4 + 3][nB] = pb1.w;       \
    } while (0)

    {
        float4 pa0, pa1, pb0, pb1;
        LOADG(0, pa0, pa1, pb0, pb1);
        STORES(0, pa0, pa1, pb0, pb1);
    }
    __syncthreads();

    int cur = 0;
    for (int kt = 0; kt < DD; kt += BK) {
        bool has = (kt + BK) < DD;
        float4 qa0, qa1, qb0, qb1;
        if (has) LOADG(kt + BK, qa0, qa1, qb0, qb1);

        // compute on buffer `cur`
#pragma unroll
        for (int k = 0; k < BK; k++) {
            unsigned long long a2[8], b2[4];
#pragma unroll
            for (int i = 0; i < 8; i++) {
                float a = As[cur][k][m0 + i];
                asm("mov.b64 %0, {%1, %1};" : "=l"(a2[i]) : "f"(a));
            }
#pragma unroll
            for (int j = 0; j < 4; j++)
                b2[j] = *(const unsigned long long*)&Bs[cur][k][n0 + 2 * j];
#pragma unroll
            for (int i = 0; i < 8; i++)
#pragma unroll
                for (int j = 0; j < 4; j++)
                    asm("fma.rn.f32x2 %0, %1, %2, %0;"
                        : "+l"(acc2[i][j]) : "l"(a2[i]), "l"(b2[j]));
        }

        if (has) STORES(cur ^ 1, qa0, qa1, qb0, qb1);
        __syncthreads();
        cur ^= 1;
    }

#pragma unroll
    for (int i = 0; i < 8; i++) {
        float bj = bias[j0 + m0 + i];
        float r[8];
#pragma unroll
        for (int j = 0; j < 4; j++) {
            float lo, hi;
            asm("mov.b64 {%0, %1}, %2;" : "=f"(lo), "=f"(hi) : "l"(acc2[i][j]));
            r[2 * j]     = lo + bj;
            r[2 * j + 1] = hi + bj;
        }
        float* row = Ct + (size_t)(b * DD + j0 + m0 + i) * SS + s0 + n0;
        *(float4*)row       = make_float4(r[0], r[1], r[2], r[3]);
        *(float4*)(row + 4) = make_float4(r[4], r[5], r[6], r[7]);
    }
#undef LOADG
#undef STORES
}

// ---------------- kernel 2: packed forward FFT of (q + i*k), per (b,h,d) ----------------
// Writes per-channel spectrum product Q[f]*conj(K[f]) into g_P (no atomics).
__global__ void fft_qk_kernel() {
    int bhd = blockIdx.x;                 // 0..4095, == b*D + h*64 + d
    const float* qr = g_Qt + (size_t)bhd * SS;
    const float* kr = g_Kt + (size_t)bhd * SS;

    __shared__ float2 z[2048];            // 16KB
    __shared__ float2 tw[1024];           // 8KB

    int tid = threadIdx.x;
    for (int i = tid; i < 1024; i += 256) tw[i] = g_twf[i];
    for (int s = tid; s < 2048; s += 256) {
        int rs = __brev((unsigned)s) >> 21;         // 11-bit reversal
        z[rs] = make_float2(qr[s], kr[s]);
    }
    __syncthreads();

    fft2048f(z, tw);

    // Unpack: Z = FFT(q + i k). Q[f] = (Z[f]+conj(Z[N-f]))/2, K[f] = (Z[f]-conj(Z[N-f]))/(2i)
    for (int f = tid; f < 2048; f += 256) {
        float2 Zf = z[f];
        float2 Zc = z[(2048 - f) & 2047];
        float Qr =  0.5f * (Zf.x + Zc.x);
        float Qi =  0.5f * (Zf.y - Zc.y);
        float Kr =  0.5f * (Zf.y + Zc.y);
        float Ki = -0.5f * (Zf.x - Zc.x);
        // P = Q * conj(K)
        g_P[(size_t)bhd * SS + f] = make_float2(Qr * Kr + Qi * Ki, Qi * Kr - Qr * Ki);
    }
}

// ---------------- kernel 3: reduce over d, inverse FFT, top-k, softmax, gather ----------------
__global__ void corr_topk_kernel(const float* __restrict__ xv,
                                 const float* __restrict__ wv,
                                 const float* __restrict__ bv) {
    int bh = blockIdx.x;       // 0..63
    int b = bh >> 4, h = bh & 15;

    __shared__ float2 z[2048];                      // 16KB
    __shared__ float2 tw[1024];                     // 8KB
    __shared__ unsigned long long key[2048];        // 16KB
    __shared__ float zv[1024];                      // 4KB
    __shared__ float red[256];                      // 1KB

    int tid = threadIdx.x;
    for (int i = tid; i < 1024; i += 256) tw[i] = g_twf[i];

    // Sum spectra over channels d; load conj(P) bit-reversed (iFFT via conj trick).
    const float2* Pbase = g_P + (size_t)bh * DH * SS;
    for (int f = tid; f < 2048; f += 256) {
        float sr = 0.0f, si = 0.0f;
        for (int d = 0; d < DH; d++) {
            float2 p = Pbase[(size_t)d * SS + f];
            sr += p.x;
            si += p.y;
        }
        int rf = __brev((unsigned)f) >> 21;
        z[rf] = make_float2(sr, -si);
    }
    __syncthreads();

    fft2048f(z, tw);

    // mean_corr[t] = Re(FFT(conj(P)))[t] / N / (dh*sqrt(dh));  N=2048, dh*sqrt(dh)=512
    // Encode as sortable 64-bit key: value desc primary, index asc on ties.
    for (int t = tid; t < 2048; t += 256) {
        float v = z[t].x * (1.0f / (2048.0f * 512.0f));
        key[t] = ((unsigned long long)fenc(v) << 32) | (unsigned)(2047 - t);
    }
    __syncthreads();

    // Bitonic sort, descending on the combined key (== lax.top_k order)
    for (int k = 2; k <= 2048; k <<= 1) {
        for (int j = k >> 1; j > 0; j >>= 1) {
            for (int t = tid; t < 2048; t += 256) {
                int ixj = t ^ j;
                if (ixj > t) {
                    unsigned long long A = key[t], Bv = key[ixj];
                    bool desc = ((t & k) == 0);
                    bool sw = desc ? (Bv > A) : (A > Bv);
                    if (sw) { key[t] = Bv; key[ixj] = A; }
                }
            }
            __syncthreads();
        }
    }

    // Softmax over top KTOP values
    float maxv = fdec((unsigned)(key[0] >> 32));
    float lsum = 0.0f;
    for (int k = tid; k < KTOP; k += 256) lsum += expf(fdec((unsigned)(key[k] >> 32)) - maxv);
    red[tid] = lsum;
    for (int off = 128; off > 0; off >>= 1) {
        __syncthreads();
        if (tid < off) red[tid] += red[tid + off];
    }
    __syncthreads();
    float total = red[0];
    __syncthreads();

    // z[k] = (weight_k, index_k) for k < KTOP (z free after key build)
    for (int k = tid; k < KTOP; k += 256) {
        unsigned long long K = key[k];
        float v = fdec((unsigned)(K >> 32));
        int idx = 2047 - (int)(K & 0xFFFFFFFFull);
        z[k] = make_float2(expf(v - maxv) / total, (float)idx);
    }
    __syncthreads();

    // zv[c] = sum_k w_k * xv[b, idx_k, c]
    for (int c = tid; c < DD; c += 256) {
        float acc = 0.0f;
        for (int k = 0; k < KTOP; k++) {
            float2 wk = z[k];
            acc += wk.x * xv[((size_t)(b * SS + (int)wk.y)) * DD + c];
        }
        zv[c] = acc;
    }
    __syncthreads();

    // attended[j = h*64+dd] = sum_c zv[c] * wv[c, j] + bv[j]   (sum of weights == 1)
    if (tid < DH) {
        int j = h * DH + tid;
        float acc = 0.0f;
        for (int c = 0; c < DD; c++) acc += zv[c] * wv[(size_t)c * DD + j];
        g_att[b * DD + j] = acc + bv[j];
    }
}

// ---------------- kernel 4: y[b] = attended[b] @ wo + bo ----------------
__global__ void proj_y_kernel(const float* __restrict__ wo, const float* __restrict__ bo) {
    int b = blockIdx.x;
    int j = threadIdx.x;  // 1024 threads
    __shared__ float av[DD];
    av[j] = g_att[b * DD + j];
    __syncthreads();
    float acc = 0.0f;
    for (int i = 0; i < DD; i++) acc += av[i] * wo[(size_t)i * DD + j];
    g_y[b * DD + j] = acc + bo[j];
}

// ---------------- kernel 5: broadcast across sequence ----------------
__global__ void bcast_kernel(float* __restrict__ out) {
    int idx = blockIdx.x * blockDim.x + threadIdx.x;  // over B*S*D/4 float4s
    int j4 = idx & 255;          // D/4 = 256
    int bs = idx >> 8;           // 0..8191
    int b  = bs >> 11;           // /2048
    ((float4*)out)[idx] = ((const float4*)g_y)[b * 256 + j4];
}

// ---------------- launch ----------------
extern "C" void kernel_launch(void* const* d_in, const int* in_sizes, int n_in,
                              void* d_out, int out_size) {
    const float* xq = (const float*)d_in[0];
    const float* xk = (const float*)d_in[1];
    const float* xv = (const float*)d_in[2];
    const float* wq = (const float*)d_in[3];
    const float* bq = (const float*)d_in[4];
    const float* wk = (const float*)d_in[5];
    const float* bk = (const float*)d_in[6];
    const float* wv = (const float*)d_in[7];
    const float* bv = (const float*)d_in[8];
    const float* wo = (const float*)d_in[9];
    const float* bo = (const float*)d_in[10];
    float* out = (float*)d_out;

    tw_init_kernel<<<4, 256>>>();
    sgemm_tn_kernel<<<dim3(DD / BM, SS / BN, BB), 256>>>(xq, wq, bq, 0);
    sgemm_tn_kernel<<<dim3(DD / BM, SS / BN, BB), 256>>>(xk, wk, bk, 1);
    fft_qk_kernel<<<BB * DD, 256>>>();
    corr_topk_kernel<<<BB * HH, 256>>>(xv, wv, bv);
    proj_y_kernel<<<BB, DD>>>(wo, bo);
    bcast_kernel<<<(BB * SS * DD / 4) / 256, 256>>>(out);
}